// round 8
// baseline (speedup 1.0000x reference)
#include <cuda_runtime.h>
#include <cuda_bf16.h>
#include <math.h>

#define H_DIM 2
#define L_LAYERS 4
#define R_RELS 16
#define B_BASES 8
#define N_NODES 1000000
#define E_EDGES 16000000

#define TILE_SHIFT 11                       // 2048-node src tiles (16 KB of x)
#define N_TILES ((N_NODES + (1 << TILE_SHIFT) - 1) >> TILE_SHIFT)   // 489

// ---- device scratch (allocation-free rule) --------------------------------
__device__ float2 g_x[N_NODES];
__device__ float2 g_h[N_NODES];
__device__ float2 g_skip[N_NODES];
__device__ int2   g_pk[E_EDGES];     // binned: {src | type<<20, dst}
__device__ float  g_nrm[E_EDGES];    // binned norm (fp32, exact)
__device__ int    g_hist[N_TILES];
__device__ int    g_cursor[N_TILES];
__device__ float4 g_W[L_LAYERS * R_RELS];
__device__ float  g_acc;

// ---------------------------------------------------------------------------
__global__ void compute_weights_kernel(const float* __restrict__ V,
                                       const float* __restrict__ comp) {
    int tid = threadIdx.x;
    if (tid >= L_LAYERS * R_RELS) return;
    int l = tid / R_RELS, r = tid % R_RELS;
    float w0 = 0.f, w1 = 0.f, w2 = 0.f, w3 = 0.f;
    #pragma unroll
    for (int b = 0; b < B_BASES; b++) {
        float c = comp[(l * R_RELS + r) * B_BASES + b];
        const float* v = V + ((l * B_BASES + b) * 4);
        w0 += c * v[0]; w1 += c * v[1]; w2 += c * v[2]; w3 += c * v[3];
    }
    g_W[tid] = make_float4(w0, w1, w2, w3);
}

// h = 0; hist = 0; acc = 0
__global__ void zero_kernel() {
    int i = blockIdx.x * blockDim.x + threadIdx.x;
    if (i == 0) g_acc = 0.f;
    if (i < N_TILES) g_hist[i] = 0;
    if (i < N_NODES) g_h[i] = make_float2(0.f, 0.f);
}

// ---- src-tile histogram (smem-aggregated) ---------------------------------
__global__ void hist_kernel(const int4* __restrict__ src4) {
    __shared__ int sh[N_TILES];
    for (int b = threadIdx.x; b < N_TILES; b += blockDim.x) sh[b] = 0;
    __syncthreads();
    for (int i = blockIdx.x * blockDim.x + threadIdx.x; i < E_EDGES / 4;
         i += gridDim.x * blockDim.x) {
        int4 s = src4[i];
        atomicAdd(&sh[s.x >> TILE_SHIFT], 1);
        atomicAdd(&sh[s.y >> TILE_SHIFT], 1);
        atomicAdd(&sh[s.z >> TILE_SHIFT], 1);
        atomicAdd(&sh[s.w >> TILE_SHIFT], 1);
    }
    __syncthreads();
    for (int b = threadIdx.x; b < N_TILES; b += blockDim.x) {
        int c = sh[b];
        if (c) atomicAdd(&g_hist[b], c);
    }
}

// ---- exclusive scan over 489 tile counts (1 block) ------------------------
__global__ void scan_kernel() {
    __shared__ int s[512];
    int t = threadIdx.x;
    int v = (t < N_TILES) ? g_hist[t] : 0;
    s[t] = v;
    __syncthreads();
    #pragma unroll
    for (int off = 1; off < 512; off <<= 1) {
        int x = (t >= off) ? s[t - off] : 0;
        __syncthreads();
        s[t] += x;
        __syncthreads();
    }
    if (t < N_TILES) g_cursor[t] = s[t] - v;
}

// ---- block-aggregated scatter into src-tile bins (register-staged) --------
__global__ void __launch_bounds__(256) scatter_kernel(
        const int4* __restrict__ src4,
        const int4* __restrict__ dst4,
        const int4* __restrict__ type4,
        const float4* __restrict__ norm4) {
    __shared__ int s_cnt[N_TILES];
    __shared__ int s_base[N_TILES];
    for (int b = threadIdx.x; b < N_TILES; b += 256) s_cnt[b] = 0;
    __syncthreads();

    int i = blockIdx.x * 256 + threadIdx.x;
    bool act = (i < E_EDGES / 8);

    int ss[8], dd[8], tt[8], tl[8];
    float nn[8];
    if (act) {
        int q = i * 2;
        int4   s0 = src4[q],  s1 = src4[q + 1];
        int4   d0 = dst4[q],  d1 = dst4[q + 1];
        int4   t0 = type4[q], t1 = type4[q + 1];
        float4 n0 = norm4[q], n1 = norm4[q + 1];
        ss[0]=s0.x; ss[1]=s0.y; ss[2]=s0.z; ss[3]=s0.w;
        ss[4]=s1.x; ss[5]=s1.y; ss[6]=s1.z; ss[7]=s1.w;
        dd[0]=d0.x; dd[1]=d0.y; dd[2]=d0.z; dd[3]=d0.w;
        dd[4]=d1.x; dd[5]=d1.y; dd[6]=d1.z; dd[7]=d1.w;
        tt[0]=t0.x; tt[1]=t0.y; tt[2]=t0.z; tt[3]=t0.w;
        tt[4]=t1.x; tt[5]=t1.y; tt[6]=t1.z; tt[7]=t1.w;
        nn[0]=n0.x; nn[1]=n0.y; nn[2]=n0.z; nn[3]=n0.w;
        nn[4]=n1.x; nn[5]=n1.y; nn[6]=n1.z; nn[7]=n1.w;
        #pragma unroll
        for (int k = 0; k < 8; k++) {
            tl[k] = ss[k] >> TILE_SHIFT;
            atomicAdd(&s_cnt[tl[k]], 1);
        }
    }
    __syncthreads();

    for (int b = threadIdx.x; b < N_TILES; b += 256) {
        int c = s_cnt[b];
        s_base[b] = c ? atomicAdd(&g_cursor[b], c) : 0;
        s_cnt[b] = 0;
    }
    __syncthreads();

    if (act) {
        #pragma unroll
        for (int k = 0; k < 8; k++) {
            int pos = s_base[tl[k]] + atomicAdd(&s_cnt[tl[k]], 1);
            g_pk[pos] = make_int2(ss[k] | (tt[k] << 20), dd[k]);
            g_nrm[pos] = nn[k];
        }
    }
}

// ---- layer: edge-parallel over binned edges; gathers hit a 16 KB L1 window
__global__ void __launch_bounds__(1024) layer_kernel(
        const float2* __restrict__ xin, int l) {
    __shared__ float4 sW[R_RELS];
    if (threadIdx.x < R_RELS) sW[threadIdx.x] = g_W[l * R_RELS + threadIdx.x];
    __syncthreads();

    int i = blockIdx.x * 1024 + threadIdx.x;
    if (i >= E_EDGES / 4) return;

    const int4* pk4 = (const int4*)g_pk;       // {pk0,dst0,pk1,dst1}
    int4 a = pk4[2 * i];
    int4 b = pk4[2 * i + 1];
    float4 nm = ((const float4*)g_nrm)[i];

    int   pk[4] = {a.x, a.z, b.x, b.z};
    int   dd[4] = {a.y, a.w, b.y, b.w};
    float nn[4] = {nm.x, nm.y, nm.z, nm.w};

    float2 xs[4];
    #pragma unroll
    for (int k = 0; k < 4; k++) xs[k] = __ldg(&xin[pk[k] & 0xFFFFF]);

    #pragma unroll
    for (int k = 0; k < 4; k++) {
        float4 w = sW[pk[k] >> 20];            // bits 20..23 = type
        float mx = (xs[k].x * w.x + xs[k].y * w.z) * nn[k];
        float my = (xs[k].x * w.y + xs[k].y * w.w) * nn[k];
        atomicAdd(&g_h[dd[k]], make_float2(mx, my));
    }
}

// ---- epilogues (consume h, produce x, re-zero h) --------------------------
__global__ void epi_relu_kernel(int l, const float* __restrict__ bias) {
    int i = blockIdx.x * blockDim.x + threadIdx.x;
    if (i >= N_NODES) return;
    float2 h = g_h[i];
    g_x[i] = make_float2(fmaxf(h.x + __ldg(&bias[2 * l]), 0.f),
                         fmaxf(h.y + __ldg(&bias[2 * l + 1]), 0.f));
    g_h[i] = make_float2(0.f, 0.f);
}

__global__ void epi_skip_kernel(const float* __restrict__ bias,
                                const float2* __restrict__ feat) {
    int i = blockIdx.x * blockDim.x + threadIdx.x;
    if (i >= N_NODES) return;
    float2 h = g_h[i];
    float2 f = feat[i];
    float2 v = make_float2(fmaxf(h.x + __ldg(&bias[2]), 0.f) + f.x,
                           fmaxf(h.y + __ldg(&bias[3]), 0.f) + f.y);
    g_x[i] = v;
    g_skip[i] = v;
    g_h[i] = make_float2(0.f, 0.f);
}

// ---- fused final epilogue + dot:  acc += w . ((h3 + b3) + skip) -----------
__global__ void dot_kernel(const float4* __restrict__ w4,
                           const float* __restrict__ bias) {
    float b3x = __ldg(&bias[6]);
    float b3y = __ldg(&bias[7]);
    const int npairs = N_NODES / 2;
    float sum = 0.f;
    for (int i = blockIdx.x * blockDim.x + threadIdx.x; i < npairs;
         i += gridDim.x * blockDim.x) {
        float4 w = w4[i];
        float2 ha = g_h[2 * i],    hb = g_h[2 * i + 1];
        float2 sa = g_skip[2 * i], sb = g_skip[2 * i + 1];
        sum += w.x * (ha.x + b3x + sa.x) + w.y * (ha.y + b3y + sa.y)
             + w.z * (hb.x + b3x + sb.x) + w.w * (hb.y + b3y + sb.y);
    }
    #pragma unroll
    for (int off = 16; off > 0; off >>= 1)
        sum += __shfl_down_sync(0xFFFFFFFFu, sum, off);
    __shared__ float ws[8];
    int lane = threadIdx.x & 31, wid = threadIdx.x >> 5;
    if (lane == 0) ws[wid] = sum;
    __syncthreads();
    if (wid == 0) {
        sum = (lane < (blockDim.x >> 5)) ? ws[lane] : 0.f;
        #pragma unroll
        for (int off = 4; off > 0; off >>= 1)
            sum += __shfl_down_sync(0xFFFFFFFFu, sum, off);
        if (lane == 0) atomicAdd(&g_acc, sum);
    }
}

__global__ void finalize_kernel(const float* __restrict__ b_mlp,
                                float* __restrict__ out) {
    float logit = g_acc + b_mlp[0];
    out[0] = 1.f / (1.f + expf(-logit));
}

// ---------------------------------------------------------------------------
extern "C" void kernel_launch(void* const* d_in, const int* in_sizes, int n_in,
                              void* d_out, int out_size) {
    const float* features  = (const float*)d_in[0];
    const float* norm      = (const float*)d_in[1];
    const float* V         = (const float*)d_in[2];
    const float* comp      = (const float*)d_in[3];
    const float* bias      = (const float*)d_in[4];
    const float* w_mlp     = (const float*)d_in[5];
    const float* b_mlp     = (const float*)d_in[6];
    const int*   edge_src  = (const int*)d_in[7];
    const int*   edge_dst  = (const int*)d_in[8];
    const int*   edge_type = (const int*)d_in[9];
    float*       out       = (float*)d_out;

    const int TB = 256;
    const int node_blocks = (N_NODES + TB - 1) / TB;
    const int sc_blocks = (E_EDGES / 8 + TB - 1) / TB;        // 7813
    const int ly_blocks = (E_EDGES / 4 + 1023) / 1024;        // 3907

    void* px = nullptr;
    cudaGetSymbolAddress(&px, g_x);
    const float2* fx = (const float2*)px;

    compute_weights_kernel<<<1, 64>>>(V, comp);
    zero_kernel<<<node_blocks, TB>>>();

    // one-time src-tile binning (amortized over 4 layers)
    hist_kernel<<<2048, TB>>>((const int4*)edge_src);
    scan_kernel<<<1, 512>>>();
    scatter_kernel<<<sc_blocks, TB>>>((const int4*)edge_src,
                                      (const int4*)edge_dst,
                                      (const int4*)edge_type,
                                      (const float4*)norm);

    layer_kernel<<<ly_blocks, 1024>>>((const float2*)features, 0);
    epi_relu_kernel<<<node_blocks, TB>>>(0, bias);

    layer_kernel<<<ly_blocks, 1024>>>(fx, 1);
    epi_skip_kernel<<<node_blocks, TB>>>(bias, (const float2*)features);

    layer_kernel<<<ly_blocks, 1024>>>(fx, 2);
    epi_relu_kernel<<<node_blocks, TB>>>(2, bias);

    layer_kernel<<<ly_blocks, 1024>>>(fx, 3);

    dot_kernel<<<1024, TB>>>((const float4*)w_mlp, bias);
    finalize_kernel<<<1, 1>>>(b_mlp, out);
}

// round 9
// speedup vs baseline: 1.4803x; 1.4803x over previous
#include <cuda_runtime.h>
#include <cuda_bf16.h>
#include <math.h>

#define H_DIM 2
#define L_LAYERS 4
#define R_RELS 16
#define B_BASES 8
#define N_NODES 1000000
#define E_EDGES 16000000

// ---- device scratch (allocation-free rule) --------------------------------
__device__ float2 g_x[N_NODES];
__device__ float2 g_h[N_NODES];
__device__ float2 g_skip[N_NODES];
__device__ float4 g_W[L_LAYERS * R_RELS];   // (w00,w01,w10,w11) per [l][r]
__device__ float  g_acc;

// ---------------------------------------------------------------------------
__global__ void compute_weights_kernel(const float* __restrict__ V,
                                       const float* __restrict__ comp) {
    int tid = threadIdx.x;
    if (tid >= L_LAYERS * R_RELS) return;
    int l = tid / R_RELS, r = tid % R_RELS;
    float w0 = 0.f, w1 = 0.f, w2 = 0.f, w3 = 0.f;
    #pragma unroll
    for (int b = 0; b < B_BASES; b++) {
        float c = comp[(l * R_RELS + r) * B_BASES + b];
        const float* v = V + ((l * B_BASES + b) * 4);
        w0 += c * v[0]; w1 += c * v[1]; w2 += c * v[2]; w3 += c * v[3];
    }
    g_W[tid] = make_float4(w0, w1, w2, w3);
}

// h = 0; acc = 0
__global__ void zero_kernel() {
    int i = blockIdx.x * blockDim.x + threadIdx.x;
    if (i == 0) g_acc = 0.f;
    if (i < N_NODES) g_h[i] = make_float2(0.f, 0.f);
}

// ---------------------------------------------------------------------------
// Edge kernel (R1/R7-proven shape): 4 edges/thread.
// Streams use __ldcs (evict-first) so they don't evict gather sectors from L1.
__global__ void __launch_bounds__(256) edge_kernel(
        const float2* __restrict__ xin,
        const int4* __restrict__ src4,
        const int4* __restrict__ dst4,
        const int4* __restrict__ type4,
        const float4* __restrict__ norm4,
        int l) {
    __shared__ float4 sW[R_RELS];
    if (threadIdx.x < R_RELS) sW[threadIdx.x] = g_W[l * R_RELS + threadIdx.x];
    __syncthreads();

    int i = blockIdx.x * blockDim.x + threadIdx.x;
    if (i >= E_EDGES / 4) return;

    int4   s  = __ldcs(&src4[i]);
    int4   d  = __ldcs(&dst4[i]);
    int4   t  = __ldcs(&type4[i]);
    float4 nm = __ldcs(&norm4[i]);

    int   ss[4] = {s.x, s.y, s.z, s.w};
    int   dd[4] = {d.x, d.y, d.z, d.w};
    int   tt[4] = {t.x, t.y, t.z, t.w};
    float nn[4] = {nm.x, nm.y, nm.z, nm.w};

    #pragma unroll
    for (int k = 0; k < 4; k++) {
        float2 xs = __ldg(&xin[ss[k]]);
        float4 w = sW[tt[k]];
        float mx = (xs.x * w.x + xs.y * w.z) * nn[k];
        float my = (xs.x * w.y + xs.y * w.w) * nn[k];
        atomicAdd(&g_h[dd[k]], make_float2(mx, my));
    }
}

// ---------------------------------------------------------------------------
// Epilogues: consume h, produce x, re-zero h in the same pass.
// After layers 0 and 2:  x = relu(h + b)
__global__ void epi_relu_kernel(int l, const float* __restrict__ bias) {
    int i = blockIdx.x * blockDim.x + threadIdx.x;
    if (i >= N_NODES) return;
    float2 h = g_h[i];
    g_x[i] = make_float2(fmaxf(h.x + __ldg(&bias[2 * l]), 0.f),
                         fmaxf(h.y + __ldg(&bias[2 * l + 1]), 0.f));
    g_h[i] = make_float2(0.f, 0.f);
}

// After layer 1:  x = relu(h + b1) + features;  skip = x
__global__ void epi_skip_kernel(const float* __restrict__ bias,
                                const float2* __restrict__ feat) {
    int i = blockIdx.x * blockDim.x + threadIdx.x;
    if (i >= N_NODES) return;
    float2 h = g_h[i];
    float2 f = feat[i];
    float2 v = make_float2(fmaxf(h.x + __ldg(&bias[2]), 0.f) + f.x,
                           fmaxf(h.y + __ldg(&bias[3]), 0.f) + f.y);
    g_x[i] = v;
    g_skip[i] = v;
    g_h[i] = make_float2(0.f, 0.f);
}

// ---------------------------------------------------------------------------
// Fused final epilogue + dot:  acc += w . ((h3 + b3) + skip)
__global__ void dot_kernel(const float4* __restrict__ w4,
                           const float* __restrict__ bias) {
    float b3x = __ldg(&bias[6]);
    float b3y = __ldg(&bias[7]);
    const int npairs = N_NODES / 2;   // one float4 of w covers 2 nodes
    float sum = 0.f;
    for (int i = blockIdx.x * blockDim.x + threadIdx.x; i < npairs;
         i += gridDim.x * blockDim.x) {
        float4 w = __ldcs(&w4[i]);
        float2 ha = g_h[2 * i],    hb = g_h[2 * i + 1];
        float2 sa = g_skip[2 * i], sb = g_skip[2 * i + 1];
        sum += w.x * (ha.x + b3x + sa.x) + w.y * (ha.y + b3y + sa.y)
             + w.z * (hb.x + b3x + sb.x) + w.w * (hb.y + b3y + sb.y);
    }
    #pragma unroll
    for (int off = 16; off > 0; off >>= 1)
        sum += __shfl_down_sync(0xFFFFFFFFu, sum, off);
    __shared__ float ws[8];
    int lane = threadIdx.x & 31, wid = threadIdx.x >> 5;
    if (lane == 0) ws[wid] = sum;
    __syncthreads();
    if (wid == 0) {
        sum = (lane < (blockDim.x >> 5)) ? ws[lane] : 0.f;
        #pragma unroll
        for (int off = 4; off > 0; off >>= 1)
            sum += __shfl_down_sync(0xFFFFFFFFu, sum, off);
        if (lane == 0) atomicAdd(&g_acc, sum);
    }
}

__global__ void finalize_kernel(const float* __restrict__ b_mlp,
                                float* __restrict__ out) {
    float logit = g_acc + b_mlp[0];
    out[0] = 1.f / (1.f + expf(-logit));
}

// ---------------------------------------------------------------------------
extern "C" void kernel_launch(void* const* d_in, const int* in_sizes, int n_in,
                              void* d_out, int out_size) {
    const float* features  = (const float*)d_in[0];
    const float* norm      = (const float*)d_in[1];
    const float* V         = (const float*)d_in[2];
    const float* comp      = (const float*)d_in[3];
    const float* bias      = (const float*)d_in[4];
    const float* w_mlp     = (const float*)d_in[5];
    const float* b_mlp     = (const float*)d_in[6];
    const int*   edge_src  = (const int*)d_in[7];
    const int*   edge_dst  = (const int*)d_in[8];
    const int*   edge_type = (const int*)d_in[9];
    float*       out       = (float*)d_out;

    const int TB = 256;
    const int node_blocks = (N_NODES + TB - 1) / TB;
    const int edge_blocks = (E_EDGES / 4 + TB - 1) / TB;   // 15625

    const int4*   s4 = (const int4*)edge_src;
    const int4*   d4 = (const int4*)edge_dst;
    const int4*   t4 = (const int4*)edge_type;
    const float4* n4 = (const float4*)norm;

    void* px = nullptr;
    cudaGetSymbolAddress(&px, g_x);
    const float2* fx = (const float2*)px;

    compute_weights_kernel<<<1, 64>>>(V, comp);
    zero_kernel<<<node_blocks, TB>>>();

    // L0: gather features directly
    edge_kernel<<<edge_blocks, TB>>>((const float2*)features, s4, d4, t4, n4, 0);
    epi_relu_kernel<<<node_blocks, TB>>>(0, bias);

    edge_kernel<<<edge_blocks, TB>>>(fx, s4, d4, t4, n4, 1);
    epi_skip_kernel<<<node_blocks, TB>>>(bias, (const float2*)features);

    edge_kernel<<<edge_blocks, TB>>>(fx, s4, d4, t4, n4, 2);
    epi_relu_kernel<<<node_blocks, TB>>>(2, bias);

    edge_kernel<<<edge_blocks, TB>>>(fx, s4, d4, t4, n4, 3);

    dot_kernel<<<1024, TB>>>((const float4*)w_mlp, bias);
    finalize_kernel<<<1, 1>>>(b_mlp, out);
}